// round 12
// baseline (speedup 1.0000x reference)
#include <cuda_runtime.h>

// LWTA over groups of 4 consecutive fp32 on [4096, 8192] fp32.
// Final form: this kernel is HBM-mixed-stream bound. Six measured SM-side
// variants all saturate at ~6.0 TB/s (75% of 8 TB/s spec), which is the
// achievable ceiling for a balanced read+write stream on this part.
// Shape: 512 thr/CTA, 4 float4 groups/thread (MLP=4 — measured optimum,
// sits at the L1tex queue-contention threshold oe*MLP=16), exact tiling
// (no guards), L1-bypass cache ops (once-touched data), stores issued
// eagerly per group to shorten register lifetimes and smooth the R/W mix.

#define GPT 4        // float4 groups per thread
#define NT  512      // threads per block

__global__ void __launch_bounds__(NT) lwta_kernel(const float4* __restrict__ in,
                                                  float4* __restrict__ out) {
    int base = blockIdx.x * (NT * GPT) + threadIdx.x;

    float4 v[GPT];

    // 4 independent coalesced loads first -> MLP=4
#pragma unroll
    for (int k = 0; k < GPT; k++) {
        v[k] = __ldcg(&in[base + k * NT]);
    }

    // compute + eager store per group: STGs start draining while the
    // remaining winner computations run
#pragma unroll
    for (int k = 0; k < GPT; k++) {
        float4 x = v[k];
        // argmax, first-max-wins (strict >), matching jnp.argmax
        float m = x.x;
        int w = 0;
        if (x.y > m) { m = x.y; w = 1; }
        if (x.z > m) { m = x.z; w = 2; }
        if (x.w > m) { m = x.w; w = 3; }
        float4 r;
        r.x = (w == 0) ? x.x : 0.0f;
        r.y = (w == 1) ? x.y : 0.0f;
        r.z = (w == 2) ? x.z : 0.0f;
        r.w = (w == 3) ? x.w : 0.0f;
        __stcg(&out[base + k * NT], r);
    }
}

extern "C" void kernel_launch(void* const* d_in, const int* in_sizes, int n_in,
                              void* d_out, int out_size) {
    const float4* in = (const float4*)d_in[0];
    float4* out = (float4*)d_out;
    int n_elems = in_sizes[0];                 // 4096*8192 = 33554432
    int n_groups = n_elems / 4;                // 8388608 float4 groups

    int groups_per_block = NT * GPT;           // 2048
    int blocks = n_groups / groups_per_block;  // 4096, exact
    lwta_kernel<<<blocks, NT>>>(in, out);
}

// round 15
// speedup vs baseline: 1.0007x; 1.0007x over previous
#include <cuda_runtime.h>

// LWTA over groups of 4 consecutive fp32 on [4096, 8192] fp32.
// FINAL (= R11, the measured optimum; R12's eager-store variant regressed).
//
// This kernel is HBM-mixed-stream bound: seven measured SM-side variants
// (MLP 1/4/8, 256/512 thr, 128/256-bit accesses, default/.cs/.cg policies,
// multi-wave vs persistent grid) all saturate at ~6.0 TB/s, the achievable
// ceiling for a balanced read+write stream on this part.
//
// Shape: 512 thr/CTA, 4 float4 groups/thread front-batched (MLP=4, exactly
// at the L1tex queue-contention threshold oe*MLP_p1 = 16 — deeper regresses
// via cross-CTA spread), exact tiling (no guards), L1-bypass cache ops
// (once-touched data), batched stores after all winner computations.

#define GPT 4        // float4 groups per thread
#define NT  512      // threads per block

__global__ void __launch_bounds__(NT) lwta_kernel(const float4* __restrict__ in,
                                                  float4* __restrict__ out) {
    int base = blockIdx.x * (NT * GPT) + threadIdx.x;

    float4 v[GPT];

    // 4 independent coalesced loads, L2-only (no L1 allocation)
#pragma unroll
    for (int k = 0; k < GPT; k++) {
        v[k] = __ldcg(&in[base + k * NT]);
    }

#pragma unroll
    for (int k = 0; k < GPT; k++) {
        float4 x = v[k];
        // argmax, first-max-wins (strict >), matching jnp.argmax
        float m = x.x;
        int w = 0;
        if (x.y > m) { m = x.y; w = 1; }
        if (x.z > m) { m = x.z; w = 2; }
        if (x.w > m) { m = x.w; w = 3; }
        float4 r;
        r.x = (w == 0) ? x.x : 0.0f;
        r.y = (w == 1) ? x.y : 0.0f;
        r.z = (w == 2) ? x.z : 0.0f;
        r.w = (w == 3) ? x.w : 0.0f;
        v[k] = r;
    }

#pragma unroll
    for (int k = 0; k < GPT; k++) {
        __stcg(&out[base + k * NT], v[k]);
    }
}

extern "C" void kernel_launch(void* const* d_in, const int* in_sizes, int n_in,
                              void* d_out, int out_size) {
    const float4* in = (const float4*)d_in[0];
    float4* out = (float4*)d_out;
    int n_elems = in_sizes[0];                 // 4096*8192 = 33554432
    int n_groups = n_elems / 4;                // 8388608 float4 groups

    int groups_per_block = NT * GPT;           // 2048
    int blocks = n_groups / groups_per_block;  // 4096, exact
    lwta_kernel<<<blocks, NT>>>(in, out);
}